// round 8
// baseline (speedup 1.0000x reference)
#include <cuda_runtime.h>
#include <cuda_bf16.h>
#include <math.h>
#include <stdint.h>

#define Bdim 2
#define Hlat 128
#define Wlon 256
#define Cdim 256
#define HWsz (Hlat*Wlon)
#define MAXCOL 1792          // padded union cap (multiple of 64)

// Scratch (allocation-free rule: __device__ globals)
__device__ float g_q[(size_t)Bdim*HWsz*Cdim];
__device__ float g_k[(size_t)Bdim*HWsz*Cdim];
__device__ float g_v[(size_t)Bdim*HWsz*Cdim];
__device__ int   g_cnt[Hlat*Hlat];
__device__ int   g_arc[Hlat*Hlat];

// ---------------------------------------------------------------------------
// Tensor-core helpers (sm_80-baseline PTX, compiles at compute_103)
// ---------------------------------------------------------------------------
__device__ __forceinline__ uint32_t smem_u32(const void* p) {
    uint32_t a;
    asm("{ .reg .u64 t; cvta.to.shared.u64 t, %1; cvt.u32.u64 %0, t; }" : "=r"(a) : "l"(p));
    return a;
}
__device__ __forceinline__ void ldsm_x4(uint32_t* r, uint32_t addr) {
    asm volatile("ldmatrix.sync.aligned.m8n8.x4.shared.b16 {%0,%1,%2,%3}, [%4];"
        : "=r"(r[0]), "=r"(r[1]), "=r"(r[2]), "=r"(r[3]) : "r"(addr));
}
__device__ __forceinline__ void ldsm_x4t(uint32_t* r, uint32_t addr) {
    asm volatile("ldmatrix.sync.aligned.m8n8.x4.trans.shared.b16 {%0,%1,%2,%3}, [%4];"
        : "=r"(r[0]), "=r"(r[1]), "=r"(r[2]), "=r"(r[3]) : "r"(addr));
}
__device__ __forceinline__ void ldsm_x2(uint32_t* r, uint32_t addr) {
    asm volatile("ldmatrix.sync.aligned.m8n8.x2.shared.b16 {%0,%1}, [%2];"
        : "=r"(r[0]), "=r"(r[1]) : "r"(addr));
}
__device__ __forceinline__ void mma_bf(float* d, const uint32_t* a, uint32_t b0, uint32_t b1) {
    asm volatile(
        "mma.sync.aligned.m16n8k16.row.col.f32.bf16.bf16.f32 "
        "{%0,%1,%2,%3}, {%4,%5,%6,%7}, {%8,%9}, {%0,%1,%2,%3};"
        : "+f"(d[0]), "+f"(d[1]), "+f"(d[2]), "+f"(d[3])
        : "r"(a[0]), "r"(a[1]), "r"(a[2]), "r"(a[3]), "r"(b0), "r"(b1));
}
__device__ __forceinline__ uint32_t packbf(float lo, float hi) {
    uint32_t r;
    asm("cvt.rn.bf16x2.f32 %0, %1, %2;" : "=r"(r) : "f"(hi), "f"(lo));
    return r;
}
__device__ __forceinline__ float bflo_f(uint32_t h) { return __uint_as_float(h << 16); }
__device__ __forceinline__ float bfhi_f(uint32_t h) { return __uint_as_float(h & 0xffff0000u); }

// ---------------------------------------------------------------------------
// Arc table precompute
// ---------------------------------------------------------------------------
__global__ void zero_cnt_kernel() { g_cnt[blockIdx.x * 256 + threadIdx.x] = 0; }
__global__ void count_kernel(const int* __restrict__ rows, const int* __restrict__ cols, int nnz) {
    int i = blockIdx.x * 256 + threadIdx.x;
    if (i >= nnz) return;
    atomicAdd(&g_cnt[rows[i] * Hlat + (cols[i] >> 8)], 1);
}
__global__ void arc_kernel() {
    int i = blockIdx.x * 256 + threadIdx.x;
    int c = g_cnt[i];
    g_arc[i] = (c == 0) ? -1 : ((c >= 256) ? 128 : ((c - 1) >> 1));
}

// ---------------------------------------------------------------------------
// QKV projection via mma.sync bf16 hi/lo split (round-6 passing version)
// ---------------------------------------------------------------------------
__global__ __launch_bounds__(256) void qkv_mma_kernel(
    const float* __restrict__ x,
    const float* __restrict__ wq, const float* __restrict__ wk, const float* __restrict__ wv,
    const float* __restrict__ bq, const float* __restrict__ bk, const float* __restrict__ bv)
{
    __shared__ __align__(16) unsigned short A_hi[32][136];
    __shared__ __align__(16) unsigned short A_lo[32][136];
    __shared__ __align__(16) unsigned short W_hi[128][40];
    __shared__ __align__(16) unsigned short W_lo[128][40];

    int tid = threadIdx.x, lane = tid & 31, warp = tid >> 5;
    int p0 = blockIdx.x * 128;
    int nb = blockIdx.y;
    int b  = blockIdx.z;
    int mat = nb >> 1;
    int j0 = (nb & 1) * 128;

    const float* Wm   = (mat == 0) ? wq : (mat == 1) ? wk : wv;
    const float* Bias = (mat == 0) ? bq : (mat == 1) ? bk : bv;
    float*       Out  = (mat == 0) ? g_q : (mat == 1) ? g_k : g_v;
    float osc = (mat == 0) ? 0.0625f : 1.0f;

    const float* xb = x + (size_t)b * Cdim * HWsz;

    uint32_t a_hi_base = smem_u32(A_hi);
    uint32_t a_lo_base = smem_u32(A_lo);
    uint32_t w_hi_base = smem_u32(W_hi);
    uint32_t w_lo_base = smem_u32(W_lo);

    float acc[2][8][4];
    #pragma unroll
    for (int i = 0; i < 2; ++i)
        #pragma unroll
        for (int j = 0; j < 8; ++j)
            #pragma unroll
            for (int k = 0; k < 4; ++k) acc[i][j][k] = 0.f;

    int wp = warp & 3, wj = warp >> 2;
    int g  = lane >> 3, jl = lane & 7;
    int a_krow = jl + ((g & 2) ? 8 : 0);
    int a_mcol = (g & 1) ? 8 : 0;
    int b_nrow = jl + ((g & 2) ? 8 : 0);
    int b_kcol = (g & 1) ? 8 : 0;

    for (int chunk = 0; chunk < 8; ++chunk) {
        int c0 = chunk * 32;
        #pragma unroll
        for (int it = 0; it < 4; ++it) {
            int idx = tid + it * 256;
            int r = idx >> 5, c4 = idx & 31;
            float4 v = *(const float4*)(xb + (size_t)(c0 + r) * HWsz + p0 + c4 * 4);
            uint32_t h0 = packbf(v.x, v.y), h1 = packbf(v.z, v.w);
            float lx = v.x - bflo_f(h0), ly = v.y - bfhi_f(h0);
            float lz = v.z - bflo_f(h1), lw = v.w - bfhi_f(h1);
            uint32_t l0 = packbf(lx, ly), l1 = packbf(lz, lw);
            *(uint2*)&A_hi[r][c4 * 4] = make_uint2(h0, h1);
            *(uint2*)&A_lo[r][c4 * 4] = make_uint2(l0, l1);
        }
        #pragma unroll
        for (int it = 0; it < 4; ++it) {
            int idx = tid + it * 256;
            int j = idx >> 3, f4 = idx & 7;
            float4 v = *(const float4*)(Wm + (size_t)(j0 + j) * Cdim + c0 + f4 * 4);
            uint32_t h0 = packbf(v.x, v.y), h1 = packbf(v.z, v.w);
            float lx = v.x - bflo_f(h0), ly = v.y - bfhi_f(h0);
            float lz = v.z - bflo_f(h1), lw = v.w - bfhi_f(h1);
            uint32_t l0 = packbf(lx, ly), l1 = packbf(lz, lw);
            *(uint2*)&W_hi[j][f4 * 4] = make_uint2(h0, h1);
            *(uint2*)&W_lo[j][f4 * 4] = make_uint2(l0, l1);
        }
        __syncthreads();

        #pragma unroll
        for (int ks = 0; ks < 2; ++ks) {
            int k0 = ks * 16;
            uint32_t ah[2][4], al[2][4];
            #pragma unroll
            for (int mt = 0; mt < 2; ++mt) {
                int m0 = wp * 32 + mt * 16;
                uint32_t off = (uint32_t)((k0 + a_krow) * 272 + (m0 + a_mcol) * 2);
                ldsm_x4t(ah[mt], a_hi_base + off);
                ldsm_x4t(al[mt], a_lo_base + off);
            }
            #pragma unroll
            for (int np = 0; np < 4; ++np) {
                int n0 = wj * 64 + np * 16;
                uint32_t off = (uint32_t)((n0 + b_nrow) * 80 + (k0 + b_kcol) * 2);
                uint32_t bh[4], bl[4];
                ldsm_x4(bh, w_hi_base + off);
                ldsm_x4(bl, w_lo_base + off);
                #pragma unroll
                for (int mt = 0; mt < 2; ++mt) {
                    mma_bf(acc[mt][np * 2],     ah[mt], bh[0], bh[1]);
                    mma_bf(acc[mt][np * 2],     al[mt], bh[0], bh[1]);
                    mma_bf(acc[mt][np * 2],     ah[mt], bl[0], bl[1]);
                    mma_bf(acc[mt][np * 2 + 1], ah[mt], bh[2], bh[3]);
                    mma_bf(acc[mt][np * 2 + 1], al[mt], bh[2], bh[3]);
                    mma_bf(acc[mt][np * 2 + 1], ah[mt], bl[2], bl[3]);
                }
            }
        }
        __syncthreads();
    }

    float* opb = Out + (size_t)b * HWsz * Cdim;
    int r0 = lane >> 2, cp = (lane & 3) * 2;
    #pragma unroll
    for (int mt = 0; mt < 2; ++mt) {
        int p = p0 + wp * 32 + mt * 16 + r0;
        #pragma unroll
        for (int nt = 0; nt < 8; ++nt) {
            int jc = j0 + wj * 64 + nt * 8 + cp;
            float b0v = Bias[jc], b1v = Bias[jc + 1];
            float2 s0, s1;
            s0.x = fmaf(acc[mt][nt][0], osc, b0v);
            s0.y = fmaf(acc[mt][nt][1], osc, b1v);
            s1.x = fmaf(acc[mt][nt][2], osc, b0v);
            s1.y = fmaf(acc[mt][nt][3], osc, b1v);
            *(float2*)(opb + (size_t)p * Cdim + jc) = s0;
            *(float2*)(opb + (size_t)(p + 8) * Cdim + jc) = s1;
        }
    }
}

// ---------------------------------------------------------------------------
// Tensor-core flash attention, T=16. Dynamic smem layout (bytes):
// ---------------------------------------------------------------------------
#define OFF_KVH   0            // K/V chunk hi: 64 x 264 ushort (pitch 528B)
#define OFF_KVL   33792
#define OFF_QH    67584        // Q hi: 16 x 264 ushort
#define OFF_QL    76032
#define OFF_AH    84480        // alpha hi: 16 x 72 ushort (pitch 144B)
#define OFF_AL    86784
#define OFF_COL   89088        // int[1792]
#define OFF_AUX   96256        // int[1792]
#define OFF_ARC   103424       // int[128]
#define OFF_WID   103936       // int[128]
#define OFF_START 104448       // int[132]
#define OFF_CRED  104976       // float[8*16]
#define OFF_STAT  105488       // float m_run[16], f/inv[16], d[16]
#define ATT_SMEM  105728

__global__ __launch_bounds__(256) void attn_tc_kernel(
    const float* __restrict__ qw_lat, float* __restrict__ out)
{
    extern __shared__ char dsm[];
    unsigned short* KVh = (unsigned short*)(dsm + OFF_KVH);
    unsigned short* KVl = (unsigned short*)(dsm + OFF_KVL);
    unsigned short* Qh  = (unsigned short*)(dsm + OFF_QH);
    unsigned short* Ql  = (unsigned short*)(dsm + OFF_QL);
    unsigned short* AH  = (unsigned short*)(dsm + OFF_AH);
    unsigned short* AL  = (unsigned short*)(dsm + OFF_AL);
    int*   s_colp  = (int*)(dsm + OFF_COL);
    int*   s_aux   = (int*)(dsm + OFF_AUX);
    int*   s_arcv  = (int*)(dsm + OFF_ARC);
    int*   s_widv  = (int*)(dsm + OFF_WID);
    int*   s_start = (int*)(dsm + OFF_START);
    float* s_cred  = (float*)(dsm + OFF_CRED);
    float* s_mrun  = (float*)(dsm + OFF_STAT);
    float* s_f     = s_mrun + 16;
    float* s_d     = s_mrun + 32;

    uint32_t sb = smem_u32(dsm);
    uint32_t kvh_u = sb + OFF_KVH, kvl_u = sb + OFF_KVL;
    uint32_t qh_u = sb + OFF_QH,  ql_u = sb + OFF_QL;
    uint32_t ah_u = sb + OFF_AH,  al_u = sb + OFF_AL;

    int wo0 = blockIdx.x * 16;
    int ho = blockIdx.y, b = blockIdx.z;
    int tid = threadIdx.x, lane = tid & 31, warp = tid >> 5;

    // ---- setup ----
    if (tid < Hlat) {
        int a = g_arc[ho * Hlat + tid];
        s_arcv[tid] = a;
        int w = (a < 0) ? 0 : (2 * a + 16);
        s_widv[tid] = (w > 256) ? 256 : w;
    }
    if (tid < 16) { s_mrun[tid] = -INFINITY; s_d[tid] = 0.f; }
    // stage Q (16 x 256) as bf16 hi/lo, [t][c] layout
    {
        const float* qg = g_q + (((size_t)b * Hlat + ho) * Wlon + wo0) * Cdim;
        #pragma unroll
        for (int i = 0; i < 4; ++i) {
            int e = tid + (i << 8);          // 0..1023
            int row = e >> 6;                // t 0..15
            int c4 = (e & 63) << 2;
            float4 v = *(const float4*)(qg + (size_t)row * Cdim + c4);
            uint32_t h0 = packbf(v.x, v.y), h1 = packbf(v.z, v.w);
            float lx = v.x - bflo_f(h0), ly = v.y - bfhi_f(h0);
            float lz = v.z - bflo_f(h1), lw = v.w - bfhi_f(h1);
            *(uint2*)(Qh + row * 264 + c4) = make_uint2(h0, h1);
            *(uint2*)(Ql + row * 264 + c4) = make_uint2(packbf(lx, ly), packbf(lz, lw));
        }
    }
    __syncthreads();
    if (warp == 0) {
        int b0 = lane * 4;
        int w0 = s_widv[b0], w1 = s_widv[b0+1], w2 = s_widv[b0+2], w3 = s_widv[b0+3];
        int p1 = w0 + w1, p2 = p1 + w2, tot = p2 + w3;
        int inc = tot;
        #pragma unroll
        for (int o = 1; o < 32; o <<= 1) {
            int nv = __shfl_up_sync(0xffffffffu, inc, o);
            if (lane >= o) inc += nv;
        }
        int base = inc - tot;
        s_start[b0] = base; s_start[b0+1] = base + w0;
        s_start[b0+2] = base + p1; s_start[b0+3] = base + p2;
        if (lane == 31) s_start[Hlat] = inc;
    }
    __syncthreads();
    int ncol = s_start[Hlat];
    if (ncol > MAXCOL) ncol = MAXCOL;
    int ncp = (ncol + 63) & ~63;
    for (int j = tid; j < ncp; j += 256) {
        if (j < ncol) {
            int lo = 0, hi2 = Hlat;
            while (lo + 1 < hi2) {
                int mid = (lo + hi2) >> 1;
                if (s_start[mid] <= j) lo = mid; else hi2 = mid;
            }
            int a = s_arcv[lo];
            int w = wo0 - a + (j - s_start[lo]);
            s_colp[j] = lo * 256 + (w & 255);
            s_aux[j]  = (a << 8) | ((w - wo0) & 255);
        } else {
            s_colp[j] = 0;
            s_aux[j]  = -256;    // a = -1 -> invalid
        }
    }

    // fragment address components
    int jl = lane & 7, g = lane >> 3;
    int r0 = lane >> 2, c0 = (lane & 3) * 2;
    int a_row = jl + ((g & 1) ? 8 : 0);      // A non-trans rows / V-trans k-rows
    int a_kc  = (g & 2) ? 8 : 0;             // A non-trans k-col / V-trans n-col
    int b_nr  = lane & 7;                    // phase-1 B x2
    int b_kc  = (lane & 8) ? 8 : 0;

    float Oacc[4][4];
    #pragma unroll
    for (int i = 0; i < 4; ++i)
        #pragma unroll
        for (int j = 0; j < 4; ++j) Oacc[i][j] = 0.f;

    const float* kbase = g_k + (size_t)b * HWsz * Cdim;
    const float* vbase = g_v + (size_t)b * HWsz * Cdim;
    int n0 = warp << 3;      // phase-1 col tile
    int nw = warp << 5;      // phase-3 c tile

    int nchunk = ncp >> 6;
    for (int ch = 0; ch < nchunk; ++ch) {
        int jb = ch << 6;
        __syncthreads();     // prior phase-3 done with KV buffer
        // ---- stage K chunk ----
        #pragma unroll
        for (int i = 0; i < 16; ++i) {
            int e = tid + (i << 8);
            int row = e >> 6, c4 = (e & 63) << 2;
            int p = s_colp[jb + row];
            float4 v = *(const float4*)(kbase + (size_t)p * Cdim + c4);
            uint32_t h0 = packbf(v.x, v.y), h1 = packbf(v.z, v.w);
            float lx = v.x - bflo_f(h0), ly = v.y - bfhi_f(h0);
            float lz = v.z - bflo_f(h1), lw = v.w - bfhi_f(h1);
            *(uint2*)(KVh + row * 264 + c4) = make_uint2(h0, h1);
            *(uint2*)(KVl + row * 264 + c4) = make_uint2(packbf(lx, ly), packbf(lz, lw));
        }
        __syncthreads();
        // ---- phase 1: logits = Q.K^T (warp tile: 16t x 8cols) ----
        float lg[4] = {0.f, 0.f, 0.f, 0.f};
        #pragma unroll 4
        for (int ks = 0; ks < 16; ++ks) {
            uint32_t ah4[4], al4[4], bh2[2], bl2[2];
            uint32_t aoff = (uint32_t)(a_row * 528 + (ks * 16 + a_kc) * 2);
            ldsm_x4(ah4, qh_u + aoff);
            ldsm_x4(al4, ql_u + aoff);
            uint32_t boff = (uint32_t)((n0 + b_nr) * 528 + (ks * 16 + b_kc) * 2);
            ldsm_x2(bh2, kvh_u + boff);
            ldsm_x2(bl2, kvl_u + boff);
            mma_bf(lg, ah4, bh2[0], bh2[1]);
            mma_bf(lg, al4, bh2[0], bh2[1]);
            mma_bf(lg, ah4, bl2[0], bl2[1]);
        }
        // ---- masks + chunk max ----
        int aux0 = s_aux[jb + n0 + c0];
        int aux1 = s_aux[jb + n0 + c0 + 1];
        int A0 = aux0 >> 8, D0 = aux0 & 255;
        int A1 = aux1 >> 8, D1 = aux1 & 255;
        int dw;
        dw = (D0 - r0) & 255;       bool v0 = (dw <= A0) || (dw >= 256 - A0);
        dw = (D1 - r0) & 255;       bool v1 = (dw <= A1) || (dw >= 256 - A1);
        dw = (D0 - (r0 + 8)) & 255; bool v2 = (dw <= A0) || (dw >= 256 - A0);
        dw = (D1 - (r0 + 8)) & 255; bool v3 = (dw <= A1) || (dw >= 256 - A1);
        float m0 = fmaxf(v0 ? lg[0] : -INFINITY, v1 ? lg[1] : -INFINITY);
        float m1 = fmaxf(v2 ? lg[2] : -INFINITY, v3 ? lg[3] : -INFINITY);
        m0 = fmaxf(m0, __shfl_xor_sync(0xffffffffu, m0, 1));
        m0 = fmaxf(m0, __shfl_xor_sync(0xffffffffu, m0, 2));
        m1 = fmaxf(m1, __shfl_xor_sync(0xffffffffu, m1, 1));
        m1 = fmaxf(m1, __shfl_xor_sync(0xffffffffu, m1, 2));
        if ((lane & 3) == 0) {
            s_cred[warp * 16 + r0]     = m0;
            s_cred[warp * 16 + r0 + 8] = m1;
        }
        __syncthreads();
        if (tid < 16) {
            float mc = s_cred[tid];
            #pragma unroll
            for (int w = 1; w < 8; ++w) mc = fmaxf(mc, s_cred[w * 16 + tid]);
            float mo = s_mrun[tid];
            float mn = fmaxf(mo, mc);
            float f = (mn == -INFINITY) ? 0.f : __expf(mo - mn);
            s_mrun[tid] = mn; s_f[tid] = f; s_d[tid] *= f;
        }
        __syncthreads();
        // ---- rescale O, alphas, chunk sums ----
        {
            float f0 = s_f[r0], f1 = s_f[r0 + 8];
            #pragma unroll
            for (int t = 0; t < 4; ++t) {
                Oacc[t][0] *= f0; Oacc[t][1] *= f0;
                Oacc[t][2] *= f1; Oacc[t][3] *= f1;
            }
            float mn0 = s_mrun[r0], mn1 = s_mrun[r0 + 8];
            float qw0 = qw_lat[s_colp[jb + n0 + c0] >> 8];
            float qw1 = qw_lat[s_colp[jb + n0 + c0 + 1] >> 8];
            float al0 = v0 ? __expf(lg[0] - mn0) * qw0 : 0.f;
            float al1 = v1 ? __expf(lg[1] - mn0) * qw1 : 0.f;
            float al2 = v2 ? __expf(lg[2] - mn1) * qw0 : 0.f;
            float al3 = v3 ? __expf(lg[3] - mn1) * qw1 : 0.f;
            float s0 = al0 + al1, s1 = al2 + al3;
            s0 += __shfl_xor_sync(0xffffffffu, s0, 1);
            s0 += __shfl_xor_sync(0xffffffffu, s0, 2);
            s1 += __shfl_xor_sync(0xffffffffu, s1, 1);
            s1 += __shfl_xor_sync(0xffffffffu, s1, 2);
            if ((lane & 3) == 0) {
                s_cred[warp * 16 + r0]     = s0;
                s_cred[warp * 16 + r0 + 8] = s1;
            }
            uint32_t hw0 = packbf(al0, al1);
            uint32_t lw0 = packbf(al0 - bflo_f(hw0), al1 - bfhi_f(hw0));
            uint32_t hw1 = packbf(al2, al3);
            uint32_t lw1 = packbf(al2 - bflo_f(hw1), al3 - bfhi_f(hw1));
            *(uint32_t*)(AH + r0 * 72 + n0 + c0)       = hw0;
            *(uint32_t*)(AL + r0 * 72 + n0 + c0)       = lw0;
            *(uint32_t*)(AH + (r0 + 8) * 72 + n0 + c0) = hw1;
            *(uint32_t*)(AL + (r0 + 8) * 72 + n0 + c0) = lw1;
        }
        __syncthreads();
        if (tid < 16) {
            float s = s_d[tid];
            #pragma unroll
            for (int w = 0; w < 8; ++w) s += s_cred[w * 16 + tid];
            s_d[tid] = s;
        }
        // ---- stage V over K ----
        #pragma unroll
        for (int i = 0; i < 16; ++i) {
            int e = tid + (i << 8);
            int row = e >> 6, c4 = (e & 63) << 2;
            int p = s_colp[jb + row];
            float4 v = *(const float4*)(vbase + (size_t)p * Cdim + c4);
            uint32_t h0 = packbf(v.x, v.y), h1 = packbf(v.z, v.w);
            float lx = v.x - bflo_f(h0), ly = v.y - bfhi_f(h0);
            float lz = v.z - bflo_f(h1), lw = v.w - bfhi_f(h1);
            *(uint2*)(KVh + row * 264 + c4) = make_uint2(h0, h1);
            *(uint2*)(KVl + row * 264 + c4) = make_uint2(packbf(lx, ly), packbf(lz, lw));
        }
        __syncthreads();
        // ---- phase 3: O += alpha.V (warp: all 16t x its 32 c) ----
        #pragma unroll
        for (int ks = 0; ks < 4; ++ks) {
            uint32_t ah4[4], al4[4];
            uint32_t aoff = (uint32_t)(a_row * 144 + (ks * 16 + a_kc) * 2);
            ldsm_x4(ah4, ah_u + aoff);
            ldsm_x4(al4, al_u + aoff);
            #pragma unroll
            for (int ng = 0; ng < 2; ++ng) {
                uint32_t voff = (uint32_t)((ks * 16 + a_row) * 528 + (nw + ng * 16 + a_kc) * 2);
                uint32_t vh4[4], vl4[4];
                ldsm_x4t(vh4, kvh_u + voff);
                ldsm_x4t(vl4, kvl_u + voff);
                float* d0 = Oacc[ng * 2];
                float* d1 = Oacc[ng * 2 + 1];
                mma_bf(d0, ah4, vh4[0], vh4[1]);
                mma_bf(d0, al4, vh4[0], vh4[1]);
                mma_bf(d0, ah4, vl4[0], vl4[1]);
                mma_bf(d1, ah4, vh4[2], vh4[3]);
                mma_bf(d1, al4, vh4[2], vh4[3]);
                mma_bf(d1, ah4, vl4[2], vl4[3]);
            }
        }
    }
    __syncthreads();
    if (tid < 16) s_f[tid] = 1.0f / s_d[tid];
    __syncthreads();
    // ---- epilogue: restage via smem (reuse KV region as float [256][17]) ----
    float* so = (float*)(dsm + OFF_KVH);
    {
        float i0 = s_f[r0], i1 = s_f[r0 + 8];
        #pragma unroll
        for (int t = 0; t < 4; ++t) {
            int c = nw + t * 8 + c0;
            so[c * 17 + r0]           = Oacc[t][0] * i0;
            so[(c + 1) * 17 + r0]     = Oacc[t][1] * i0;
            so[c * 17 + r0 + 8]       = Oacc[t][2] * i1;
            so[(c + 1) * 17 + r0 + 8] = Oacc[t][3] * i1;
        }
    }
    __syncthreads();
    {
        float* ob = out + (((size_t)b * Cdim + tid) * Hlat + ho) * Wlon + wo0;
        const float* sr = so + tid * 17;
        float4 o0 = {sr[0], sr[1], sr[2], sr[3]};
        float4 o1 = {sr[4], sr[5], sr[6], sr[7]};
        float4 o2 = {sr[8], sr[9], sr[10], sr[11]};
        float4 o3 = {sr[12], sr[13], sr[14], sr[15]};
        *(float4*)(ob)      = o0;
        *(float4*)(ob + 4)  = o1;
        *(float4*)(ob + 8)  = o2;
        *(float4*)(ob + 12) = o3;
    }
}

// ---------------------------------------------------------------------------
extern "C" void kernel_launch(void* const* d_in, const int* in_sizes, int n_in,
                              void* d_out, int out_size) {
    const float* query = (const float*)d_in[0];
    const float* wq    = (const float*)d_in[1];
    const float* wk    = (const float*)d_in[2];
    const float* wv    = (const float*)d_in[3];
    const float* bq    = (const float*)d_in[4];
    const float* bk    = (const float*)d_in[5];
    const float* bv    = (const float*)d_in[6];
    const float* qw    = (const float*)d_in[7];
    const int*   rows  = (const int*)d_in[8];
    const int*   cols  = (const int*)d_in[9];
    int nnz = in_sizes[8];
    float* out = (float*)d_out;

    cudaFuncSetAttribute(attn_tc_kernel,
                         cudaFuncAttributeMaxDynamicSharedMemorySize, ATT_SMEM);

    zero_cnt_kernel<<<Hlat * Hlat / 256, 256>>>();
    count_kernel<<<(nnz + 255) / 256, 256>>>(rows, cols, nnz);
    arc_kernel<<<Hlat * Hlat / 256, 256>>>();
    qkv_mma_kernel<<<dim3(HWsz / 128, 6, Bdim), 256>>>(query, wq, wk, wv, bq, bk, bv);
    attn_tc_kernel<<<dim3(Wlon / 16, Hlat, Bdim), 256, ATT_SMEM>>>(qw, out);
}

// round 9
// speedup vs baseline: 1.1037x; 1.1037x over previous
#include <cuda_runtime.h>
#include <cuda_bf16.h>
#include <math.h>
#include <stdint.h>

#define Bdim 2
#define Hlat 128
#define Wlon 256
#define Cdim 256
#define HWsz (Hlat*Wlon)
#define MAXC8 1664

// Scratch (allocation-free rule: __device__ globals)
__device__ float g_q[(size_t)Bdim*HWsz*Cdim];   // (b,h,w,c), pre-scaled by 1/16
__device__ float g_k[(size_t)Bdim*HWsz*Cdim];
__device__ float g_v[(size_t)Bdim*HWsz*Cdim];
__device__ int   g_cnt[Hlat*Hlat];
__device__ int   g_arc[Hlat*Hlat];

// ---------------------------------------------------------------------------
// Tensor-core helpers (sm_80-baseline PTX)
// ---------------------------------------------------------------------------
__device__ __forceinline__ uint32_t smem_u32(const void* p) {
    uint32_t a;
    asm("{ .reg .u64 t; cvta.to.shared.u64 t, %1; cvt.u32.u64 %0, t; }" : "=r"(a) : "l"(p));
    return a;
}
__device__ __forceinline__ void ldsm_x4(uint32_t* r, uint32_t addr) {
    asm volatile("ldmatrix.sync.aligned.m8n8.x4.shared.b16 {%0,%1,%2,%3}, [%4];"
        : "=r"(r[0]), "=r"(r[1]), "=r"(r[2]), "=r"(r[3]) : "r"(addr));
}
__device__ __forceinline__ void ldsm_x4t(uint32_t* r, uint32_t addr) {
    asm volatile("ldmatrix.sync.aligned.m8n8.x4.trans.shared.b16 {%0,%1,%2,%3}, [%4];"
        : "=r"(r[0]), "=r"(r[1]), "=r"(r[2]), "=r"(r[3]) : "r"(addr));
}
__device__ __forceinline__ void mma_bf(float* d, const uint32_t* a, uint32_t b0, uint32_t b1) {
    asm volatile(
        "mma.sync.aligned.m16n8k16.row.col.f32.bf16.bf16.f32 "
        "{%0,%1,%2,%3}, {%4,%5,%6,%7}, {%8,%9}, {%0,%1,%2,%3};"
        : "+f"(d[0]), "+f"(d[1]), "+f"(d[2]), "+f"(d[3])
        : "r"(a[0]), "r"(a[1]), "r"(a[2]), "r"(a[3]), "r"(b0), "r"(b1));
}
__device__ __forceinline__ uint32_t packbf(float lo, float hi) {
    uint32_t r;
    asm("cvt.rn.bf16x2.f32 %0, %1, %2;" : "=r"(r) : "f"(hi), "f"(lo));
    return r;
}
__device__ __forceinline__ float bflo_f(uint32_t h) { return __uint_as_float(h << 16); }
__device__ __forceinline__ float bfhi_f(uint32_t h) { return __uint_as_float(h & 0xffff0000u); }

// ---------------------------------------------------------------------------
// Arc table precompute
// ---------------------------------------------------------------------------
__global__ void zero_cnt_kernel() { g_cnt[blockIdx.x * 256 + threadIdx.x] = 0; }
__global__ void count_kernel(const int* __restrict__ rows, const int* __restrict__ cols, int nnz) {
    int i = blockIdx.x * 256 + threadIdx.x;
    if (i >= nnz) return;
    atomicAdd(&g_cnt[rows[i] * Hlat + (cols[i] >> 8)], 1);
}
__global__ void arc_kernel() {
    int i = blockIdx.x * 256 + threadIdx.x;
    int c = g_cnt[i];
    g_arc[i] = (c == 0) ? -1 : ((c >= 256) ? 128 : ((c - 1) >> 1));
}

// ---------------------------------------------------------------------------
// QKV projection via mma.sync bf16 hi/lo (3-term). Warp tile 32p x 32j so
// regs fit 2 blocks/SM. Grid: (256, 12, 2); block = 128p x 64j of one matrix.
// ---------------------------------------------------------------------------
__global__ __launch_bounds__(256, 2) void qkv_mma_kernel(
    const float* __restrict__ x,
    const float* __restrict__ wq, const float* __restrict__ wk, const float* __restrict__ wv,
    const float* __restrict__ bq, const float* __restrict__ bk, const float* __restrict__ bv)
{
    __shared__ __align__(16) unsigned short A_hi[32][136];
    __shared__ __align__(16) unsigned short A_lo[32][136];
    __shared__ __align__(16) unsigned short W_hi[64][40];
    __shared__ __align__(16) unsigned short W_lo[64][40];

    int tid = threadIdx.x, lane = tid & 31, warp = tid >> 5;
    int p0 = blockIdx.x * 128;
    int nb = blockIdx.y;
    int b  = blockIdx.z;
    int mat = nb >> 2;
    int j0 = (nb & 3) * 64;

    const float* Wm   = (mat == 0) ? wq : (mat == 1) ? wk : wv;
    const float* Bias = (mat == 0) ? bq : (mat == 1) ? bk : bv;
    float*       Out  = (mat == 0) ? g_q : (mat == 1) ? g_k : g_v;
    float osc = (mat == 0) ? 0.0625f : 1.0f;

    const float* xb = x + (size_t)b * Cdim * HWsz;

    uint32_t a_hi_base = smem_u32(A_hi);
    uint32_t a_lo_base = smem_u32(A_lo);
    uint32_t w_hi_base = smem_u32(W_hi);
    uint32_t w_lo_base = smem_u32(W_lo);

    float acc[2][4][4];
    #pragma unroll
    for (int i = 0; i < 2; ++i)
        #pragma unroll
        for (int j = 0; j < 4; ++j)
            #pragma unroll
            for (int k = 0; k < 4; ++k) acc[i][j][k] = 0.f;

    int wp = warp & 3, wj = warp >> 2;
    int g  = lane >> 3, jl = lane & 7;
    int a_krow = jl + ((g & 2) ? 8 : 0);
    int a_mcol = (g & 1) ? 8 : 0;
    int b_nrow = jl + ((g & 2) ? 8 : 0);
    int b_kcol = (g & 1) ? 8 : 0;

    for (int chunk = 0; chunk < 8; ++chunk) {
        int c0 = chunk * 32;
        // stage x tile (32c x 128p) bf16 hi/lo
        #pragma unroll
        for (int it = 0; it < 4; ++it) {
            int idx = tid + it * 256;
            int r = idx >> 5, c4 = idx & 31;
            float4 v = *(const float4*)(xb + (size_t)(c0 + r) * HWsz + p0 + c4 * 4);
            uint32_t h0 = packbf(v.x, v.y), h1 = packbf(v.z, v.w);
            float lx = v.x - bflo_f(h0), ly = v.y - bfhi_f(h0);
            float lz = v.z - bflo_f(h1), lw = v.w - bfhi_f(h1);
            *(uint2*)&A_hi[r][c4 * 4] = make_uint2(h0, h1);
            *(uint2*)&A_lo[r][c4 * 4] = make_uint2(packbf(lx, ly), packbf(lz, lw));
        }
        // stage W tile (64j x 32c) bf16 hi/lo
        #pragma unroll
        for (int it = 0; it < 2; ++it) {
            int idx = tid + it * 256;
            int j = idx >> 3, f4 = idx & 7;
            float4 v = *(const float4*)(Wm + (size_t)(j0 + j) * Cdim + c0 + f4 * 4);
            uint32_t h0 = packbf(v.x, v.y), h1 = packbf(v.z, v.w);
            float lx = v.x - bflo_f(h0), ly = v.y - bfhi_f(h0);
            float lz = v.z - bflo_f(h1), lw = v.w - bfhi_f(h1);
            *(uint2*)&W_hi[j][f4 * 4] = make_uint2(h0, h1);
            *(uint2*)&W_lo[j][f4 * 4] = make_uint2(packbf(lx, ly), packbf(lz, lw));
        }
        __syncthreads();

        #pragma unroll
        for (int ks = 0; ks < 2; ++ks) {
            int k0 = ks * 16;
            uint32_t ah[2][4], al[2][4];
            #pragma unroll
            for (int mt = 0; mt < 2; ++mt) {
                int m0 = wp * 32 + mt * 16;
                uint32_t off = (uint32_t)((k0 + a_krow) * 272 + (m0 + a_mcol) * 2);
                ldsm_x4t(ah[mt], a_hi_base + off);
                ldsm_x4t(al[mt], a_lo_base + off);
            }
            #pragma unroll
            for (int np = 0; np < 2; ++np) {
                int n0 = wj * 32 + np * 16;
                uint32_t off = (uint32_t)((n0 + b_nrow) * 80 + (k0 + b_kcol) * 2);
                uint32_t bh[4], bl[4];
                ldsm_x4(bh, w_hi_base + off);
                ldsm_x4(bl, w_lo_base + off);
                #pragma unroll
                for (int mt = 0; mt < 2; ++mt) {
                    mma_bf(acc[mt][np * 2],     ah[mt], bh[0], bh[1]);
                    mma_bf(acc[mt][np * 2],     al[mt], bh[0], bh[1]);
                    mma_bf(acc[mt][np * 2],     ah[mt], bl[0], bl[1]);
                    mma_bf(acc[mt][np * 2 + 1], ah[mt], bh[2], bh[3]);
                    mma_bf(acc[mt][np * 2 + 1], al[mt], bh[2], bh[3]);
                    mma_bf(acc[mt][np * 2 + 1], ah[mt], bl[2], bl[3]);
                }
            }
        }
        __syncthreads();
    }

    float* opb = Out + (size_t)b * HWsz * Cdim;
    int r0 = lane >> 2, cp = (lane & 3) * 2;
    #pragma unroll
    for (int mt = 0; mt < 2; ++mt) {
        int p = p0 + wp * 32 + mt * 16 + r0;
        #pragma unroll
        for (int nt = 0; nt < 4; ++nt) {
            int jc = j0 + wj * 32 + nt * 8 + cp;
            float b0v = Bias[jc], b1v = Bias[jc + 1];
            float2 s0, s1;
            s0.x = fmaf(acc[mt][nt][0], osc, b0v);
            s0.y = fmaf(acc[mt][nt][1], osc, b1v);
            s1.x = fmaf(acc[mt][nt][2], osc, b0v);
            s1.y = fmaf(acc[mt][nt][3], osc, b1v);
            *(float2*)(opb + (size_t)p * Cdim + jc) = s0;
            *(float2*)(opb + (size_t)(p + 8) * Cdim + jc) = s1;
        }
    }
}

// ---------------------------------------------------------------------------
// Scalar attention, wo-tiled T=8 (round-4 structure, wider tile).
// Dynamic smem layout (bytes):
// ---------------------------------------------------------------------------
#define AOFF_Q     0          // float[8*256]
#define AOFF_ALPHA 8192       // float[MAXC8*8]
#define AOFF_OFF   61440      // int[MAXC8]
#define AOFF_AUX   68096      // int[MAXC8]
#define AOFF_ARC   74752      // int[128]
#define AOFF_WID   75264      // int[128]
#define AOFF_START 75776      // int[129]
#define AOFF_RED   76304      // float[64]
#define AOFF_M     76560      // float[8]
#define AOFF_INV   76592      // float[8]
#define ATTN_SMEM  76640

__global__ __launch_bounds__(256, 2) void attn_kernel(
    const float* __restrict__ qw_lat, float* __restrict__ out)
{
    extern __shared__ char dsm[];
    float* s_q     = (float*)(dsm + AOFF_Q);
    float* s_alpha = (float*)(dsm + AOFF_ALPHA);
    int*   s_off   = (int*)(dsm + AOFF_OFF);
    int*   s_aux   = (int*)(dsm + AOFF_AUX);
    int*   s_arcv  = (int*)(dsm + AOFF_ARC);
    int*   s_widv  = (int*)(dsm + AOFF_WID);
    int*   s_start = (int*)(dsm + AOFF_START);
    float* s_red   = (float*)(dsm + AOFF_RED);
    float* s_m     = (float*)(dsm + AOFF_M);
    float* s_inv   = (float*)(dsm + AOFF_INV);

    int wo0 = blockIdx.x * 8;
    int ho = blockIdx.y, b = blockIdx.z;
    int tid = threadIdx.x, lane = tid & 31, warp = tid >> 5;

    if (tid < Hlat) {
        int a = g_arc[ho * Hlat + tid];
        s_arcv[tid] = a;
        int w = (a < 0) ? 0 : (2 * a + 8);
        s_widv[tid] = (w > 256) ? 256 : w;
    }
    {   // stage Q (8 x 256)
        int t = tid >> 5, c8 = (tid & 31) * 8;
        const float* qg = g_q + (((size_t)b * Hlat + ho) * Wlon + wo0 + t) * Cdim + c8;
        *(float4*)&s_q[t * 256 + c8]     = *(const float4*)qg;
        *(float4*)&s_q[t * 256 + c8 + 4] = *(const float4*)(qg + 4);
    }
    __syncthreads();

    if (warp == 0) {
        int b0 = lane * 4;
        int w0 = s_widv[b0], w1 = s_widv[b0+1], w2 = s_widv[b0+2], w3 = s_widv[b0+3];
        int p1 = w0 + w1, p2 = p1 + w2, tot = p2 + w3;
        int inc = tot;
        #pragma unroll
        for (int o = 1; o < 32; o <<= 1) {
            int nv = __shfl_up_sync(0xffffffffu, inc, o);
            if (lane >= o) inc += nv;
        }
        int base = inc - tot;
        s_start[b0] = base; s_start[b0+1] = base + w0;
        s_start[b0+2] = base + p1; s_start[b0+3] = base + p2;
        if (lane == 31) s_start[Hlat] = inc;
    }
    __syncthreads();
    int ncol = s_start[Hlat];
    if (ncol > MAXC8) ncol = MAXC8;

    for (int j = tid; j < ncol; j += 256) {
        int lo = 0, hi2 = Hlat;
        while (lo + 1 < hi2) {
            int mid = (lo + hi2) >> 1;
            if (s_start[mid] <= j) lo = mid; else hi2 = mid;
        }
        int a = s_arcv[lo];
        int w = wo0 - a + (j - s_start[lo]);
        s_off[j] = lo * 256 + (w & 255);
        s_aux[j] = (a << 8) | ((w - wo0) & 255);
    }
    __syncthreads();

    // ---------------- Phase 1: logits, warp per column, 8 t's ----------------
    float4 qa[8], qb[8];
    #pragma unroll
    for (int t = 0; t < 8; ++t) {
        qa[t] = *(const float4*)&s_q[t * 256 + lane * 4];
        qb[t] = *(const float4*)&s_q[t * 256 + 128 + lane * 4];
    }
    const float* kb = g_k + (size_t)b * HWsz * Cdim;
    bool b1 = (lane & 1), b2 = (lane & 2), b4 = (lane & 4);
    const int tq = lane & 7;
    float lmax = -INFINITY;

    for (int j = warp; j < ncol; j += 8) {
        const float* kr = kb + (size_t)s_off[j] * Cdim;
        float4 k0 = *(const float4*)(kr + lane * 4);
        float4 k1 = *(const float4*)(kr + 128 + lane * 4);
        float p[8];
        #pragma unroll
        for (int t = 0; t < 8; ++t) {
            float s = k0.x * qa[t].x;
            s = fmaf(k0.y, qa[t].y, s); s = fmaf(k0.z, qa[t].z, s); s = fmaf(k0.w, qa[t].w, s);
            s = fmaf(k1.x, qb[t].x, s); s = fmaf(k1.y, qb[t].y, s);
            s = fmaf(k1.z, qb[t].z, s); s = fmaf(k1.w, qb[t].w, s);
            p[t] = s;
        }
        // 8-way transpose-reduce: lane ends with full sum for t = lane&7
        float u[4];
        #pragma unroll
        for (int i = 0; i < 4; ++i) {
            float a0 = b1 ? p[2*i+1] : p[2*i];
            float w0 = b1 ? p[2*i]   : p[2*i+1];
            u[i] = a0 + __shfl_xor_sync(0xffffffffu, w0, 1);
        }
        float v2[2];
        #pragma unroll
        for (int i = 0; i < 2; ++i) {
            float a0 = b2 ? u[2*i+1] : u[2*i];
            float x0 = b2 ? u[2*i]   : u[2*i+1];
            v2[i] = a0 + __shfl_xor_sync(0xffffffffu, x0, 2);
        }
        float s = b4 ? v2[1] : v2[0];
        float y = b4 ? v2[0] : v2[1];
        s += __shfl_xor_sync(0xffffffffu, y, 4);
        s += __shfl_xor_sync(0xffffffffu, s, 8);
        s += __shfl_xor_sync(0xffffffffu, s, 16);
        // validity mask for t = tq
        int aux = s_aux[j];
        int a = aux >> 8;
        int dw = ((aux & 255) - tq) & 255;
        bool valid = (dw <= a) || (dw >= 256 - a);
        s = valid ? s : -1e30f;
        if (lane < 8) s_alpha[j * 8 + lane] = s;
        lmax = fmaxf(lmax, s);
    }
    lmax = fmaxf(lmax, __shfl_xor_sync(0xffffffffu, lmax, 8));
    lmax = fmaxf(lmax, __shfl_xor_sync(0xffffffffu, lmax, 16));
    if (lane < 8) s_red[warp * 8 + lane] = lmax;
    __syncthreads();
    if (tid < 8) {
        float m = s_red[tid];
        #pragma unroll
        for (int w = 1; w < 8; ++w) m = fmaxf(m, s_red[w * 8 + tid]);
        s_m[tid] = m;
    }
    __syncthreads();

    // ---------------- Phase 2: alpha + denom ----------------
    float mt = s_m[tid & 7];
    float dloc = 0.f;
    for (int idx = tid; idx < ncol * 8; idx += 256) {
        int j = idx >> 3;
        float a = __expf(s_alpha[idx] - mt) * qw_lat[s_off[j] >> 8];
        s_alpha[idx] = a;
        dloc += a;
    }
    dloc += __shfl_xor_sync(0xffffffffu, dloc, 8);
    dloc += __shfl_xor_sync(0xffffffffu, dloc, 16);
    if (lane < 8) s_red[warp * 8 + lane] = dloc;
    __syncthreads();
    if (tid < 8) {
        float v = s_red[tid];
        #pragma unroll
        for (int w = 1; w < 8; ++w) v += s_red[w * 8 + tid];
        s_inv[tid] = 1.0f / v;
    }
    __syncthreads();

    // ---------------- Phase 3: V accumulation (one V load -> 8 accs) --------
    int g = tid >> 6;
    int c4 = (tid & 63) * 4;
    const float* vb = g_v + (size_t)b * HWsz * Cdim + c4;
    float4 A[8];
    #pragma unroll
    for (int t = 0; t < 8; ++t) A[t] = make_float4(0.f, 0.f, 0.f, 0.f);
    #pragma unroll 2
    for (int j = g; j < ncol; j += 4) {
        float4 al0 = *(const float4*)&s_alpha[j * 8];
        float4 al1 = *(const float4*)&s_alpha[j * 8 + 4];
        const float4 vv = *(const float4*)(vb + (size_t)s_off[j] * Cdim);
        A[0].x = fmaf(al0.x, vv.x, A[0].x); A[0].y = fmaf(al0.x, vv.y, A[0].y);
        A[0].z = fmaf(al0.x, vv.z, A[0].z); A[0].w = fmaf(al0.x, vv.w, A[0].w);
        A[1].x = fmaf(al0.y, vv.x, A[1].x); A[1].y = fmaf(al0.y, vv.y, A[1].y);
        A[1].z = fmaf(al0.y, vv.z, A[1].z); A[1].w = fmaf(al0.y, vv.w, A[1].w);
        A[2].x = fmaf(al0.z, vv.x, A[2].x); A[2].y = fmaf(al0.z, vv.y, A[2].y);
        A[2].z = fmaf(al0.z, vv.z, A[2].z); A[2].w = fmaf(al0.z, vv.w, A[2].w);
        A[3].x = fmaf(al0.w, vv.x, A[3].x); A[3].y = fmaf(al0.w, vv.y, A[3].y);
        A[3].z = fmaf(al0.w, vv.z, A[3].z); A[3].w = fmaf(al0.w, vv.w, A[3].w);
        A[4].x = fmaf(al1.x, vv.x, A[4].x); A[4].y = fmaf(al1.x, vv.y, A[4].y);
        A[4].z = fmaf(al1.x, vv.z, A[4].z); A[4].w = fmaf(al1.x, vv.w, A[4].w);
        A[5].x = fmaf(al1.y, vv.x, A[5].x); A[5].y = fmaf(al1.y, vv.y, A[5].y);
        A[5].z = fmaf(al1.y, vv.z, A[5].z); A[5].w = fmaf(al1.y, vv.w, A[5].w);
        A[6].x = fmaf(al1.z, vv.x, A[6].x); A[6].y = fmaf(al1.z, vv.y, A[6].y);
        A[6].z = fmaf(al1.z, vv.z, A[6].z); A[6].w = fmaf(al1.z, vv.w, A[6].w);
        A[7].x = fmaf(al1.w, vv.x, A[7].x); A[7].y = fmaf(al1.w, vv.y, A[7].y);
        A[7].z = fmaf(al1.w, vv.z, A[7].z); A[7].w = fmaf(al1.w, vv.w, A[7].w);
    }
    __syncthreads();   // alphas dead; reuse as partials [t][g][c] (32KB)
    float* sp = s_alpha;
    #pragma unroll
    for (int t = 0; t < 8; ++t)
        *(float4*)&sp[((t * 4) + g) * 256 + c4] = A[t];
    __syncthreads();

    float o[8];
    #pragma unroll
    for (int t = 0; t < 8; ++t) {
        o[t] = (sp[(t*4+0)*256 + tid] + sp[(t*4+1)*256 + tid] +
                sp[(t*4+2)*256 + tid] + sp[(t*4+3)*256 + tid]) * s_inv[t];
    }
    float* ob = out + (((size_t)b * Cdim + tid) * Hlat + ho) * Wlon + wo0;
    *(float4*)(ob)     = make_float4(o[0], o[1], o[2], o[3]);
    *(float4*)(ob + 4) = make_float4(o[4], o[5], o[6], o[7]);
}

// ---------------------------------------------------------------------------
extern "C" void kernel_launch(void* const* d_in, const int* in_sizes, int n_in,
                              void* d_out, int out_size) {
    const float* query = (const float*)d_in[0];
    const float* wq    = (const float*)d_in[1];
    const float* wk    = (const float*)d_in[2];
    const float* wv    = (const float*)d_in[3];
    const float* bq    = (const float*)d_in[4];
    const float* bk    = (const float*)d_in[5];
    const float* bv    = (const float*)d_in[6];
    const float* qw    = (const float*)d_in[7];
    const int*   rows  = (const int*)d_in[8];
    const int*   cols  = (const int*)d_in[9];
    int nnz = in_sizes[8];
    float* out = (float*)d_out;

    cudaFuncSetAttribute(attn_kernel,
                         cudaFuncAttributeMaxDynamicSharedMemorySize, ATTN_SMEM);

    zero_cnt_kernel<<<Hlat * Hlat / 256, 256>>>();
    count_kernel<<<(nnz + 255) / 256, 256>>>(rows, cols, nnz);
    arc_kernel<<<Hlat * Hlat / 256, 256>>>();
    qkv_mma_kernel<<<dim3(HWsz / 128, 12, Bdim), 256>>>(query, wq, wk, wv, bq, bk, bv);
    attn_kernel<<<dim3(Wlon / 8, Hlat, Bdim), 256, ATTN_SMEM>>>(qw, out);
}

// round 10
// speedup vs baseline: 1.2277x; 1.1124x over previous
#include <cuda_runtime.h>
#include <cuda_bf16.h>
#include <math.h>
#include <stdint.h>

#define Bdim 2
#define Hlat 128
#define Wlon 256
#define Cdim 256
#define HWsz (Hlat*Wlon)
#define MAXCOL 1536

// Scratch (allocation-free rule: __device__ globals)
__device__ float g_q[(size_t)Bdim*HWsz*Cdim];   // (b,h,w,c), pre-scaled by 1/16
__device__ float g_k[(size_t)Bdim*HWsz*Cdim];
__device__ float g_v[(size_t)Bdim*HWsz*Cdim];
__device__ int   g_cnt[Hlat*Hlat];
__device__ int   g_arc[Hlat*Hlat];

// ---------------------------------------------------------------------------
// Tensor-core helpers (sm_80-baseline PTX)
// ---------------------------------------------------------------------------
__device__ __forceinline__ uint32_t smem_u32(const void* p) {
    uint32_t a;
    asm("{ .reg .u64 t; cvta.to.shared.u64 t, %1; cvt.u32.u64 %0, t; }" : "=r"(a) : "l"(p));
    return a;
}
__device__ __forceinline__ void ldsm_x4(uint32_t* r, uint32_t addr) {
    asm volatile("ldmatrix.sync.aligned.m8n8.x4.shared.b16 {%0,%1,%2,%3}, [%4];"
        : "=r"(r[0]), "=r"(r[1]), "=r"(r[2]), "=r"(r[3]) : "r"(addr));
}
__device__ __forceinline__ void ldsm_x4t(uint32_t* r, uint32_t addr) {
    asm volatile("ldmatrix.sync.aligned.m8n8.x4.trans.shared.b16 {%0,%1,%2,%3}, [%4];"
        : "=r"(r[0]), "=r"(r[1]), "=r"(r[2]), "=r"(r[3]) : "r"(addr));
}
__device__ __forceinline__ void mma_bf(float* d, const uint32_t* a, uint32_t b0, uint32_t b1) {
    asm volatile(
        "mma.sync.aligned.m16n8k16.row.col.f32.bf16.bf16.f32 "
        "{%0,%1,%2,%3}, {%4,%5,%6,%7}, {%8,%9}, {%0,%1,%2,%3};"
        : "+f"(d[0]), "+f"(d[1]), "+f"(d[2]), "+f"(d[3])
        : "r"(a[0]), "r"(a[1]), "r"(a[2]), "r"(a[3]), "r"(b0), "r"(b1));
}
__device__ __forceinline__ uint32_t packbf(float lo, float hi) {
    uint32_t r;
    asm("cvt.rn.bf16x2.f32 %0, %1, %2;" : "=r"(r) : "f"(hi), "f"(lo));
    return r;
}
__device__ __forceinline__ float bflo_f(uint32_t h) { return __uint_as_float(h << 16); }
__device__ __forceinline__ float bfhi_f(uint32_t h) { return __uint_as_float(h & 0xffff0000u); }

// ---------------------------------------------------------------------------
// Arc table precompute
// ---------------------------------------------------------------------------
__global__ void zero_cnt_kernel() { g_cnt[blockIdx.x * 256 + threadIdx.x] = 0; }
__global__ void count_kernel(const int* __restrict__ rows, const int* __restrict__ cols, int nnz) {
    int i = blockIdx.x * 256 + threadIdx.x;
    if (i >= nnz) return;
    atomicAdd(&g_cnt[rows[i] * Hlat + (cols[i] >> 8)], 1);
}
__global__ void arc_kernel() {
    int i = blockIdx.x * 256 + threadIdx.x;
    int c = g_cnt[i];
    g_arc[i] = (c == 0) ? -1 : ((c >= 256) ? 128 : ((c - 1) >> 1));
}

// ---------------------------------------------------------------------------
// QKV projection via mma.sync bf16 hi/lo (3-term). Round-9 config (252 us):
// warp tile 32p x 32j, 2 blocks/SM. Grid: (256, 12, 2).
// ---------------------------------------------------------------------------
__global__ __launch_bounds__(256, 2) void qkv_mma_kernel(
    const float* __restrict__ x,
    const float* __restrict__ wq, const float* __restrict__ wk, const float* __restrict__ wv,
    const float* __restrict__ bq, const float* __restrict__ bk, const float* __restrict__ bv)
{
    __shared__ __align__(16) unsigned short A_hi[32][136];
    __shared__ __align__(16) unsigned short A_lo[32][136];
    __shared__ __align__(16) unsigned short W_hi[64][40];
    __shared__ __align__(16) unsigned short W_lo[64][40];

    int tid = threadIdx.x, lane = tid & 31, warp = tid >> 5;
    int p0 = blockIdx.x * 128;
    int nb = blockIdx.y;
    int b  = blockIdx.z;
    int mat = nb >> 2;
    int j0 = (nb & 3) * 64;

    const float* Wm   = (mat == 0) ? wq : (mat == 1) ? wk : wv;
    const float* Bias = (mat == 0) ? bq : (mat == 1) ? bk : bv;
    float*       Out  = (mat == 0) ? g_q : (mat == 1) ? g_k : g_v;
    float osc = (mat == 0) ? 0.0625f : 1.0f;

    const float* xb = x + (size_t)b * Cdim * HWsz;

    uint32_t a_hi_base = smem_u32(A_hi);
    uint32_t a_lo_base = smem_u32(A_lo);
    uint32_t w_hi_base = smem_u32(W_hi);
    uint32_t w_lo_base = smem_u32(W_lo);

    float acc[2][4][4];
    #pragma unroll
    for (int i = 0; i < 2; ++i)
        #pragma unroll
        for (int j = 0; j < 4; ++j)
            #pragma unroll
            for (int k = 0; k < 4; ++k) acc[i][j][k] = 0.f;

    int wp = warp & 3, wj = warp >> 2;
    int g  = lane >> 3, jl = lane & 7;
    int a_krow = jl + ((g & 2) ? 8 : 0);
    int a_mcol = (g & 1) ? 8 : 0;
    int b_nrow = jl + ((g & 2) ? 8 : 0);
    int b_kcol = (g & 1) ? 8 : 0;

    for (int chunk = 0; chunk < 8; ++chunk) {
        int c0 = chunk * 32;
        #pragma unroll
        for (int it = 0; it < 4; ++it) {
            int idx = tid + it * 256;
            int r = idx >> 5, c4 = idx & 31;
            float4 v = *(const float4*)(xb + (size_t)(c0 + r) * HWsz + p0 + c4 * 4);
            uint32_t h0 = packbf(v.x, v.y), h1 = packbf(v.z, v.w);
            float lx = v.x - bflo_f(h0), ly = v.y - bfhi_f(h0);
            float lz = v.z - bflo_f(h1), lw = v.w - bfhi_f(h1);
            *(uint2*)&A_hi[r][c4 * 4] = make_uint2(h0, h1);
            *(uint2*)&A_lo[r][c4 * 4] = make_uint2(packbf(lx, ly), packbf(lz, lw));
        }
        #pragma unroll
        for (int it = 0; it < 2; ++it) {
            int idx = tid + it * 256;
            int j = idx >> 3, f4 = idx & 7;
            float4 v = *(const float4*)(Wm + (size_t)(j0 + j) * Cdim + c0 + f4 * 4);
            uint32_t h0 = packbf(v.x, v.y), h1 = packbf(v.z, v.w);
            float lx = v.x - bflo_f(h0), ly = v.y - bfhi_f(h0);
            float lz = v.z - bflo_f(h1), lw = v.w - bfhi_f(h1);
            *(uint2*)&W_hi[j][f4 * 4] = make_uint2(h0, h1);
            *(uint2*)&W_lo[j][f4 * 4] = make_uint2(packbf(lx, ly), packbf(lz, lw));
        }
        __syncthreads();

        #pragma unroll
        for (int ks = 0; ks < 2; ++ks) {
            int k0 = ks * 16;
            uint32_t ah[2][4], al[2][4];
            #pragma unroll
            for (int mt = 0; mt < 2; ++mt) {
                int m0 = wp * 32 + mt * 16;
                uint32_t off = (uint32_t)((k0 + a_krow) * 272 + (m0 + a_mcol) * 2);
                ldsm_x4t(ah[mt], a_hi_base + off);
                ldsm_x4t(al[mt], a_lo_base + off);
            }
            #pragma unroll
            for (int np = 0; np < 2; ++np) {
                int n0 = wj * 32 + np * 16;
                uint32_t off = (uint32_t)((n0 + b_nrow) * 80 + (k0 + b_kcol) * 2);
                uint32_t bh[4], bl[4];
                ldsm_x4(bh, w_hi_base + off);
                ldsm_x4(bl, w_lo_base + off);
                #pragma unroll
                for (int mt = 0; mt < 2; ++mt) {
                    mma_bf(acc[mt][np * 2],     ah[mt], bh[0], bh[1]);
                    mma_bf(acc[mt][np * 2],     al[mt], bh[0], bh[1]);
                    mma_bf(acc[mt][np * 2],     ah[mt], bl[0], bl[1]);
                    mma_bf(acc[mt][np * 2 + 1], ah[mt], bh[2], bh[3]);
                    mma_bf(acc[mt][np * 2 + 1], al[mt], bh[2], bh[3]);
                    mma_bf(acc[mt][np * 2 + 1], ah[mt], bl[2], bl[3]);
                }
            }
        }
        __syncthreads();
    }

    float* opb = Out + (size_t)b * HWsz * Cdim;
    int r0 = lane >> 2, cp = (lane & 3) * 2;
    #pragma unroll
    for (int mt = 0; mt < 2; ++mt) {
        int p = p0 + wp * 32 + mt * 16 + r0;
        #pragma unroll
        for (int nt = 0; nt < 4; ++nt) {
            int jc = j0 + wj * 32 + nt * 8 + cp;
            float b0v = Bias[jc], b1v = Bias[jc + 1];
            float2 s0, s1;
            s0.x = fmaf(acc[mt][nt][0], osc, b0v);
            s0.y = fmaf(acc[mt][nt][1], osc, b1v);
            s1.x = fmaf(acc[mt][nt][2], osc, b0v);
            s1.y = fmaf(acc[mt][nt][3], osc, b1v);
            *(float2*)(opb + (size_t)p * Cdim + jc) = s0;
            *(float2*)(opb + (size_t)(p + 8) * Cdim + jc) = s1;
        }
    }
}

// ---------------------------------------------------------------------------
// Attention over distinct columns, T=4 (round-4/6 proven config, ~820 us).
// ---------------------------------------------------------------------------
__global__ __launch_bounds__(256) void attn_kernel(
    const float* __restrict__ qw_lat,
    float* __restrict__ out)
{
    __shared__ __align__(16) float s_q[4][Cdim];
    __shared__ __align__(16) float s_alpha[MAXCOL * 4];
    __shared__ __align__(16) int   s_off[MAXCOL];
    __shared__ __align__(16) int   s_aux[MAXCOL];
    __shared__ int   s_arcv[Hlat];
    __shared__ int   s_wid[Hlat];
    __shared__ int   s_start[Hlat + 1];
    __shared__ float s_red[32];
    __shared__ float s_m[4];
    __shared__ float s_inv[4];

    int wo0 = blockIdx.x * 4;
    int ho = blockIdx.y, b = blockIdx.z;
    int tid = threadIdx.x, lane = tid & 31, warp = tid >> 5;

    if (tid < Hlat) {
        int a = g_arc[ho * Hlat + tid];
        s_arcv[tid] = a;
        int w = (a < 0) ? 0 : (2 * a + 4);
        s_wid[tid] = (w > 256) ? 256 : w;
    }
    {
        int t = tid >> 6; int c4 = (tid & 63) * 4;
        *(float4*)&s_q[t][c4] =
            *(const float4*)(g_q + (((size_t)b * Hlat + ho) * Wlon + wo0 + t) * Cdim + c4);
    }
    __syncthreads();

    if (warp == 0) {
        int b0 = lane * 4;
        int w0 = s_wid[b0], w1 = s_wid[b0 + 1], w2 = s_wid[b0 + 2], w3 = s_wid[b0 + 3];
        int p1 = w0 + w1, p2 = p1 + w2, tot = p2 + w3;
        int inc = tot;
        #pragma unroll
        for (int o = 1; o < 32; o <<= 1) {
            int nv = __shfl_up_sync(0xffffffffu, inc, o);
            if (lane >= o) inc += nv;
        }
        int base = inc - tot;
        s_start[b0] = base; s_start[b0 + 1] = base + w0;
        s_start[b0 + 2] = base + p1; s_start[b0 + 3] = base + p2;
        if (lane == 31) s_start[Hlat] = inc;
    }
    __syncthreads();
    int ncol = s_start[Hlat];
    if (ncol > MAXCOL) ncol = MAXCOL;

    for (int j = tid; j < ncol; j += 256) {
        int lo = 0, hi2 = Hlat;
        while (lo + 1 < hi2) {
            int mid = (lo + hi2) >> 1;
            if (s_start[mid] <= j) lo = mid; else hi2 = mid;
        }
        int a = s_arcv[lo];
        int w = wo0 - a + (j - s_start[lo]);
        s_off[j] = lo * 256 + (w & 255);
        s_aux[j] = (a << 8) | ((w - wo0) & 255);
    }
    __syncthreads();

    const int tq = lane & 3;
    float4 qa[4], qb[4];
    #pragma unroll
    for (int t = 0; t < 4; ++t) {
        qa[t] = *(const float4*)&s_q[t][lane * 4];
        qb[t] = *(const float4*)&s_q[t][128 + lane * 4];
    }
    const float* kb = g_k + (size_t)b * HWsz * Cdim;
    bool b1 = (lane & 1), b2 = (lane & 2);
    float lmax = -INFINITY;

    #pragma unroll 2
    for (int j = warp; j < ncol; j += 8) {
        const float* kr = kb + (size_t)s_off[j] * Cdim;
        float4 k0 = *(const float4*)(kr + lane * 4);
        float4 k1 = *(const float4*)(kr + 128 + lane * 4);
        float p[4];
        #pragma unroll
        for (int t = 0; t < 4; ++t) {
            float s = k0.x * qa[t].x;
            s = fmaf(k0.y, qa[t].y, s); s = fmaf(k0.z, qa[t].z, s); s = fmaf(k0.w, qa[t].w, s);
            s = fmaf(k1.x, qb[t].x, s); s = fmaf(k1.y, qb[t].y, s);
            s = fmaf(k1.z, qb[t].z, s); s = fmaf(k1.w, qb[t].w, s);
            p[t] = s;
        }
        float uA = b1 ? p[1] : p[0], wA = b1 ? p[0] : p[1];
        uA += __shfl_xor_sync(0xffffffffu, wA, 1);
        float uB = b1 ? p[3] : p[2], wB = b1 ? p[2] : p[3];
        uB += __shfl_xor_sync(0xffffffffu, wB, 1);
        float v = b2 ? uB : uA, xx = b2 ? uA : uB;
        v += __shfl_xor_sync(0xffffffffu, xx, 2);
        v += __shfl_xor_sync(0xffffffffu, v, 4);
        v += __shfl_xor_sync(0xffffffffu, v, 8);
        v += __shfl_xor_sync(0xffffffffu, v, 16);
        int aux = s_aux[j];
        int a = aux >> 8;
        int dw = ((aux & 255) - tq) & 255;
        bool valid = (dw <= a) || (dw >= 256 - a);
        v = valid ? v : -1e30f;
        if (lane < 4) s_alpha[j * 4 + lane] = v;
        lmax = fmaxf(lmax, v);
    }
    if (lane < 4) s_red[warp * 4 + lane] = lmax;
    __syncthreads();
    if (tid < 4) {
        float m = s_red[tid];
        #pragma unroll
        for (int w = 1; w < 8; ++w) m = fmaxf(m, s_red[w * 4 + tid]);
        s_m[tid] = m;
    }
    __syncthreads();

    float mt = s_m[tid & 3];
    float dloc = 0.f;
    for (int idx = tid; idx < ncol * 4; idx += 256) {
        int j = idx >> 2;
        float a = __expf(s_alpha[idx] - mt) * qw_lat[s_off[j] >> 8];
        s_alpha[idx] = a;
        dloc += a;
    }
    dloc += __shfl_xor_sync(0xffffffffu, dloc, 4);
    dloc += __shfl_xor_sync(0xffffffffu, dloc, 8);
    dloc += __shfl_xor_sync(0xffffffffu, dloc, 16);
    if (lane < 4) s_red[warp * 4 + lane] = dloc;
    __syncthreads();
    if (tid < 32) {
        float v = s_red[tid];
        v += __shfl_xor_sync(0xffffffffu, v, 4);
        v += __shfl_xor_sync(0xffffffffu, v, 8);
        v += __shfl_xor_sync(0xffffffffu, v, 16);
        if (tid < 4) s_inv[tid] = 1.0f / v;
    }
    __syncthreads();

    int g = tid >> 6;
    int c4 = (tid & 63) * 4;
    const float* vb = g_v + (size_t)b * HWsz * Cdim + c4;
    float4 A0 = {0,0,0,0}, A1 = {0,0,0,0}, A2 = {0,0,0,0}, A3 = {0,0,0,0};
    #pragma unroll 2
    for (int j = g; j < ncol; j += 4) {
        float4 al = *(const float4*)&s_alpha[j * 4];
        const float4 vv = *(const float4*)(vb + (size_t)s_off[j] * Cdim);
        A0.x = fmaf(al.x, vv.x, A0.x); A0.y = fmaf(al.x, vv.y, A0.y);
        A0.z = fmaf(al.x, vv.z, A0.z); A0.w = fmaf(al.x, vv.w, A0.w);
        A1.x = fmaf(al.y, vv.x, A1.x); A1.y = fmaf(al.y, vv.y, A1.y);
        A1.z = fmaf(al.y, vv.z, A1.z); A1.w = fmaf(al.y, vv.w, A1.w);
        A2.x = fmaf(al.z, vv.x, A2.x); A2.y = fmaf(al.z, vv.y, A2.y);
        A2.z = fmaf(al.z, vv.z, A2.z); A2.w = fmaf(al.z, vv.w, A2.w);
        A3.x = fmaf(al.w, vv.x, A3.x); A3.y = fmaf(al.w, vv.y, A3.y);
        A3.z = fmaf(al.w, vv.z, A3.z); A3.w = fmaf(al.w, vv.w, A3.w);
    }
    __syncthreads();
    float* sp = s_alpha;
    *(float4*)&sp[(0 * 4 + g) * 256 + c4] = A0;
    *(float4*)&sp[(1 * 4 + g) * 256 + c4] = A1;
    *(float4*)&sp[(2 * 4 + g) * 256 + c4] = A2;
    *(float4*)&sp[(3 * 4 + g) * 256 + c4] = A3;
    __syncthreads();

    float4 o;
    {
        float v0 = sp[(0*4+0)*256+tid] + sp[(0*4+1)*256+tid] + sp[(0*4+2)*256+tid] + sp[(0*4+3)*256+tid];
        float v1 = sp[(1*4+0)*256+tid] + sp[(1*4+1)*256+tid] + sp[(1*4+2)*256+tid] + sp[(1*4+3)*256+tid];
        float v2 = sp[(2*4+0)*256+tid] + sp[(2*4+1)*256+tid] + sp[(2*4+2)*256+tid] + sp[(2*4+3)*256+tid];
        float v3 = sp[(3*4+0)*256+tid] + sp[(3*4+1)*256+tid] + sp[(3*4+2)*256+tid] + sp[(3*4+3)*256+tid];
        o.x = v0 * s_inv[0]; o.y = v1 * s_inv[1]; o.z = v2 * s_inv[2]; o.w = v3 * s_inv[3];
    }
    *(float4*)(out + (((size_t)b * Cdim + tid) * Hlat + ho) * Wlon + wo0) = o;
}

// ---------------------------------------------------------------------------
extern "C" void kernel_launch(void* const* d_in, const int* in_sizes, int n_in,
                              void* d_out, int out_size) {
    const float* query = (const float*)d_in[0];
    const float* wq    = (const float*)d_in[1];
    const float* wk    = (const float*)d_in[2];
    const float* wv    = (const float*)d_in[3];
    const float* bq    = (const float*)d_in[4];
    const float* bk    = (const float*)d_in[5];
    const float* bv    = (const float*)d_in[6];
    const float* qw    = (const float*)d_in[7];
    const int*   rows  = (const int*)d_in[8];
    const int*   cols  = (const int*)d_in[9];
    int nnz = in_sizes[8];
    float* out = (float*)d_out;

    zero_cnt_kernel<<<Hlat * Hlat / 256, 256>>>();
    count_kernel<<<(nnz + 255) / 256, 256>>>(rows, cols, nnz);
    arc_kernel<<<Hlat * Hlat / 256, 256>>>();
    qkv_mma_kernel<<<dim3(HWsz / 128, 12, Bdim), 256>>>(query, wq, wk, wv, bq, bk, bv);
    attn_kernel<<<dim3(Wlon / 4, Hlat, Bdim), 256>>>(qw, out);
}